// round 3
// baseline (speedup 1.0000x reference)
#include <cuda_runtime.h>

#define B_ 4
#define S_ 2048
#define D_ 1024
#define H_ 16
#define HD_ 64

// ---------------------------------------------------------------------------
// Scratch (device globals: allocation-free per harness rules)
// ---------------------------------------------------------------------------
__device__ float g_q[B_ * H_ * S_ * HD_];      // 32 MB each
__device__ float g_k[B_ * H_ * S_ * HD_];
__device__ float g_v[B_ * H_ * S_ * HD_];
__device__ float g_attn[B_ * S_ * D_];         // 32 MB

// ---------------------------------------------------------------------------
// SGEMM: C[M,N] = A[M,K] @ W[K,N] + bias, 128x128x8 tiles, 8x8 per thread.
// MODE 0: plain store into C; A==nullptr means "read g_attn".
// MODE 1: QKV scatter into g_q/g_k/g_v with (B,H,S,HD) layout.
// ---------------------------------------------------------------------------
template <int MODE>
__global__ __launch_bounds__(256) void sgemm128(
    const float* __restrict__ A, const float* __restrict__ W,
    const float* __restrict__ bias, float* __restrict__ C,
    int M, int N, int K)
{
    __shared__ float As[8][128];   // transposed A tile: As[k][m]
    __shared__ float Bs[8][128];   // natural W tile:    Bs[k][n]

    const float* Asrc = A;
    if (MODE == 0 && A == nullptr) Asrc = (const float*)g_attn;

    const int tid = threadIdx.x;
    const int tx = tid & 15;
    const int ty = tid >> 4;
    const int bm = blockIdx.y * 128;
    const int bn = blockIdx.x * 128;

    const int ar = tid >> 1;
    const int ac = (tid & 1) * 4;
    const int br = tid >> 5;
    const int bc = (tid & 31) * 4;

    const float* Aptr = Asrc + (long)(bm + ar) * K + ac;
    const float* Wptr = W + (long)br * N + bn + bc;

    float acc[8][8];
#pragma unroll
    for (int i = 0; i < 8; ++i)
#pragma unroll
        for (int j = 0; j < 8; ++j) acc[i][j] = 0.f;

    for (int kb = 0; kb < K; kb += 8) {
        float4 a4 = *(const float4*)(Aptr + kb);
        float4 w4 = *(const float4*)(Wptr + (long)kb * N);
        As[ac + 0][ar] = a4.x;
        As[ac + 1][ar] = a4.y;
        As[ac + 2][ar] = a4.z;
        As[ac + 3][ar] = a4.w;
        *(float4*)&Bs[br][bc] = w4;
        __syncthreads();

#pragma unroll
        for (int k = 0; k < 8; ++k) {
            float af[8], bf[8];
            *(float4*)&af[0] = *(const float4*)&As[k][ty * 8];
            *(float4*)&af[4] = *(const float4*)&As[k][ty * 8 + 4];
            *(float4*)&bf[0] = *(const float4*)&Bs[k][tx * 8];
            *(float4*)&bf[4] = *(const float4*)&Bs[k][tx * 8 + 4];
#pragma unroll
            for (int i = 0; i < 8; ++i)
#pragma unroll
                for (int j = 0; j < 8; ++j)
                    acc[i][j] += af[i] * bf[j];
        }
        __syncthreads();
    }

    const int n0 = bn + tx * 8;
    float bfrag[8];
#pragma unroll
    for (int j = 0; j < 8; ++j) bfrag[j] = bias[n0 + j];

    if (MODE == 0) {
#pragma unroll
        for (int i = 0; i < 8; ++i) {
            const long row = bm + ty * 8 + i;
            float4 o0 = make_float4(acc[i][0] + bfrag[0], acc[i][1] + bfrag[1],
                                    acc[i][2] + bfrag[2], acc[i][3] + bfrag[3]);
            float4 o1 = make_float4(acc[i][4] + bfrag[4], acc[i][5] + bfrag[5],
                                    acc[i][6] + bfrag[6], acc[i][7] + bfrag[7]);
            *(float4*)&C[row * N + n0] = o0;
            *(float4*)&C[row * N + n0 + 4] = o1;
        }
    } else {
        const int h = n0 / 192;            // 8 consecutive cols share h/which
        const int which = (n0 % 192) >> 6;
        const int d0 = n0 & 63;
        float* dst = (which == 0) ? g_q : (which == 1) ? g_k : g_v;
#pragma unroll
        for (int i = 0; i < 8; ++i) {
            const int m = bm + ty * 8 + i;
            const int b = m >> 11;
            const int s = m & (S_ - 1);
            const long base = (((long)b * H_ + h) * S_ + s) * HD_ + d0;
            float4 o0 = make_float4(acc[i][0] + bfrag[0], acc[i][1] + bfrag[1],
                                    acc[i][2] + bfrag[2], acc[i][3] + bfrag[3]);
            float4 o1 = make_float4(acc[i][4] + bfrag[4], acc[i][5] + bfrag[5],
                                    acc[i][6] + bfrag[6], acc[i][7] + bfrag[7]);
            *(float4*)&dst[base] = o0;
            *(float4*)&dst[base + 4] = o1;
        }
    }
}

// ---------------------------------------------------------------------------
// Flash-style fp32 attention. Block = (b, h, 64-query tile), 256 threads.
// Only ceil(vlen/64) key tiles processed: exp(masked - max) underflows to
// exactly 0 in the reference (-1e6 mask), so skipping is bit-equivalent.
// ---------------------------------------------------------------------------
#define PT 68
#define ATTN_SMEM_BYTES ((4 * 64 * PT + 128) * 4)

__global__ __launch_bounds__(256) void attn_kernel(const int* __restrict__ val_lens)
{
    extern __shared__ float sm[];
    float* QsT = sm;                 // [k][r] pre-scaled by 1/8
    float* KsT = QsT + 64 * PT;      // [k][c]
    float* Vs  = KsT + 64 * PT;      // [key][d]
    float* StT = Vs + 64 * PT;       // [c][r] scores -> probs
    float* alphas = StT + 64 * PT;
    float* lrow   = alphas + 64;

    const int q0 = blockIdx.x * 64;
    const int h  = blockIdx.y;
    const int b  = blockIdx.z;
    const int vlen = val_lens[b];
    const int tid = threadIdx.x;
    const int tx = tid & 15;
    const int ty = tid >> 4;
    const int lr = tid >> 2;
    const int d0 = (tid & 3) * 16;

    const long headoff = ((long)(b * H_ + h)) * S_ * HD_;
    const float* qbase = g_q + headoff;
    const float* kbase = g_k + headoff;
    const float* vbase = g_v + headoff;

    {
        const float* src = qbase + (long)(q0 + lr) * HD_ + d0;
#pragma unroll
        for (int j = 0; j < 16; j += 4) {
            float4 t4 = *(const float4*)(src + j);
            QsT[(d0 + j + 0) * PT + lr] = t4.x * 0.125f;
            QsT[(d0 + j + 1) * PT + lr] = t4.y * 0.125f;
            QsT[(d0 + j + 2) * PT + lr] = t4.z * 0.125f;
            QsT[(d0 + j + 3) * PT + lr] = t4.w * 0.125f;
        }
    }

    float mrow = -3.0e38f;
    float lacc = 0.f;
    float Oacc[4][4];
#pragma unroll
    for (int i = 0; i < 4; ++i)
#pragma unroll
        for (int j = 0; j < 4; ++j) Oacc[i][j] = 0.f;

    const int ntiles = (vlen + 63) >> 6;
    for (int kt = 0; kt < ntiles; ++kt) {
        {
            const float* ksrc = kbase + (long)(kt * 64 + lr) * HD_ + d0;
            const float* vsrc = vbase + (long)(kt * 64 + lr) * HD_ + d0;
#pragma unroll
            for (int j = 0; j < 16; j += 4) {
                float4 t4 = *(const float4*)(ksrc + j);
                KsT[(d0 + j + 0) * PT + lr] = t4.x;
                KsT[(d0 + j + 1) * PT + lr] = t4.y;
                KsT[(d0 + j + 2) * PT + lr] = t4.z;
                KsT[(d0 + j + 3) * PT + lr] = t4.w;
                *(float4*)&Vs[lr * PT + d0 + j] = *(const float4*)(vsrc + j);
            }
        }
        __syncthreads();

        {   // S = (Q*scale) K^T
            float acc[4][4];
#pragma unroll
            for (int i = 0; i < 4; ++i)
#pragma unroll
                for (int j = 0; j < 4; ++j) acc[i][j] = 0.f;
#pragma unroll 4
            for (int k = 0; k < 64; ++k) {
                float qa[4], kb[4];
                *(float4*)qa = *(const float4*)&QsT[k * PT + 4 * ty];
                *(float4*)kb = *(const float4*)&KsT[k * PT + 4 * tx];
#pragma unroll
                for (int i = 0; i < 4; ++i)
#pragma unroll
                    for (int j = 0; j < 4; ++j)
                        acc[i][j] += qa[i] * kb[j];
            }
#pragma unroll
            for (int j = 0; j < 4; ++j) {
                float4 c4 = make_float4(acc[0][j], acc[1][j], acc[2][j], acc[3][j]);
                *(float4*)&StT[(4 * tx + j) * PT + 4 * ty] = c4;
            }
        }
        __syncthreads();

        {   // online softmax; 4 consecutive lanes per row
            const int kg0 = kt * 64;
            float tmax = -3.0e38f;
#pragma unroll
            for (int j = 0; j < 16; ++j) {
                const int c = d0 + j;
                const float s = StT[c * PT + lr];
                if (kg0 + c < vlen) tmax = fmaxf(tmax, s);
            }
            tmax = fmaxf(tmax, __shfl_xor_sync(0xffffffffu, tmax, 1));
            tmax = fmaxf(tmax, __shfl_xor_sync(0xffffffffu, tmax, 2));
            const float mnew = fmaxf(mrow, tmax);
            const float alpha = __expf(mrow - mnew);
            float lsum = 0.f;
#pragma unroll
            for (int j = 0; j < 16; ++j) {
                const int c = d0 + j;
                const float s = StT[c * PT + lr];
                const float p = (kg0 + c < vlen) ? __expf(s - mnew) : 0.f;
                StT[c * PT + lr] = p;
                lsum += p;
            }
            lsum += __shfl_xor_sync(0xffffffffu, lsum, 1);
            lsum += __shfl_xor_sync(0xffffffffu, lsum, 2);
            lacc = lacc * alpha + lsum;
            mrow = mnew;
            if ((tid & 3) == 0) { alphas[lr] = alpha; lrow[lr] = lacc; }
        }
        __syncthreads();

        {   // O = O*alpha + P @ V
            float a[4];
#pragma unroll
            for (int i = 0; i < 4; ++i) a[i] = alphas[4 * ty + i];
#pragma unroll
            for (int i = 0; i < 4; ++i)
#pragma unroll
                for (int j = 0; j < 4; ++j) Oacc[i][j] *= a[i];
#pragma unroll 4
            for (int k = 0; k < 64; ++k) {
                float p[4], v[4];
                *(float4*)p = *(const float4*)&StT[k * PT + 4 * ty];
                *(float4*)v = *(const float4*)&Vs[k * PT + 4 * tx];
#pragma unroll
                for (int i = 0; i < 4; ++i)
#pragma unroll
                    for (int j = 0; j < 4; ++j)
                        Oacc[i][j] += p[i] * v[j];
            }
        }
        __syncthreads();
    }

    {
        float li[4];
#pragma unroll
        for (int i = 0; i < 4; ++i) li[i] = 1.0f / lrow[4 * ty + i];
#pragma unroll
        for (int i = 0; i < 4; ++i) {
            const long row = (long)b * S_ + q0 + 4 * ty + i;
            float4 o4 = make_float4(Oacc[i][0] * li[i], Oacc[i][1] * li[i],
                                    Oacc[i][2] * li[i], Oacc[i][3] * li[i]);
            *(float4*)&g_attn[row * D_ + h * HD_ + 4 * tx] = o4;
        }
    }
}

// ---------------------------------------------------------------------------
// Host launcher (graph-capturable: kernel launches only, no allocs/syncs)
// ---------------------------------------------------------------------------
extern "C" void kernel_launch(void* const* d_in, const int* in_sizes, int n_in,
                              void* d_out, int out_size)
{
    const float* x        = (const float*)d_in[0];
    const float* Wqkv     = (const float*)d_in[1];
    const float* bqkv     = (const float*)d_in[2];
    const float* Wout     = (const float*)d_in[3];
    const float* bout     = (const float*)d_in[4];
    const int*   val_lens = (const int*)d_in[5];
    float* out = (float*)d_out;

    // 1) QKV projection, scattered into (B,H,S,HD) Q/K/V
    {
        dim3 grid((3 * D_) / 128, (B_ * S_) / 128);
        sgemm128<1><<<grid, 256>>>(x, Wqkv, bqkv, nullptr, B_ * S_, 3 * D_, D_);
    }
    // 2) Flash attention -> g_attn
    {
        cudaFuncSetAttribute(attn_kernel,
                             cudaFuncAttributeMaxDynamicSharedMemorySize,
                             ATTN_SMEM_BYTES);
        dim3 grid(S_ / 64, H_, B_);
        attn_kernel<<<grid, 256, ATTN_SMEM_BYTES>>>(val_lens);
    }
    // 3) Output projection -> d_out
    {
        dim3 grid(D_ / 128, (B_ * S_) / 128);
        sgemm128<0><<<grid, 256>>>(nullptr, Wout, bout, out, B_ * S_, D_, D_);
    }
}

// round 4
// speedup vs baseline: 1.7258x; 1.7258x over previous
#include <cuda_runtime.h>
#include <cstdint>

#define B_ 4
#define S_ 2048
#define D_ 1024
#define H_ 16
#define HD_ 64

// ---------------------------------------------------------------------------
// Scratch (device globals: allocation-free per harness rules)
// ---------------------------------------------------------------------------
__device__ float g_q[B_ * H_ * S_ * HD_];      // 32 MB each
__device__ float g_k[B_ * H_ * S_ * HD_];
__device__ float g_v[B_ * H_ * S_ * HD_];
__device__ float g_attn[B_ * S_ * D_];         // 32 MB

// ---------------------------------------------------------------------------
// PTX helpers
// ---------------------------------------------------------------------------
__device__ __forceinline__ uint32_t cvt_tf32(float x) {
    uint32_t r;
    asm("cvt.rna.tf32.f32 %0, %1;" : "=r"(r) : "f"(x));
    return r;
}
__device__ __forceinline__ uint32_t smem_u32(const void* p) {
    return (uint32_t)__cvta_generic_to_shared(p);
}
__device__ __forceinline__ void cp_async16(uint32_t dst, const void* src) {
    asm volatile("cp.async.cg.shared.global [%0], [%1], 16;" :: "r"(dst), "l"(src));
}
__device__ __forceinline__ void cp_commit() {
    asm volatile("cp.async.commit_group;" ::: "memory");
}
__device__ __forceinline__ void cp_wait_all() {
    asm volatile("cp.async.wait_group 0;" ::: "memory");
}
__device__ __forceinline__ void mma_tf32(float* c, const uint32_t* a, const uint32_t* b) {
    asm("mma.sync.aligned.m16n8k8.row.col.f32.tf32.tf32.f32 "
        "{%0,%1,%2,%3}, {%4,%5,%6,%7}, {%8,%9}, {%0,%1,%2,%3};"
        : "+f"(c[0]), "+f"(c[1]), "+f"(c[2]), "+f"(c[3])
        : "r"(a[0]), "r"(a[1]), "r"(a[2]), "r"(a[3]),
          "r"(b[0]), "r"(b[1]));
}

// ---------------------------------------------------------------------------
// tf32 tensor-core GEMM: C[M,N] = A[M,K] @ W[K,N] + bias.
// Block tile 256x128x32, 8 warps (4m x 2n), warp tile 64x64, m16n8k8 mma.
// cp.async double-buffered smem. All dims divide tile sizes exactly.
// MODE 0: plain store to C; A==nullptr means "read g_attn".
// MODE 1: QKV scatter into g_q/g_k/g_v with (B,H,S,HD) layout.
// ---------------------------------------------------------------------------
#define BM 256
#define BN 128
#define BK 32
#define APITCH 36          // floats per A smem row (bank: 4g+t4, conflict-free)
#define BPITCH 136         // floats per B smem row (bank: 8t4+g, conflict-free)
#define AS_SZ (BM * APITCH)     // 9216 floats
#define BS_SZ (BK * BPITCH)     // 4352 floats
#define GEMM_SMEM_BYTES ((2 * AS_SZ + 2 * BS_SZ) * 4)   // 108544 B

template <int MODE>
__global__ __launch_bounds__(256, 1) void gemm_tf32(
    const float* __restrict__ A, const float* __restrict__ W,
    const float* __restrict__ bias, float* __restrict__ C,
    int M, int N, int K)
{
    extern __shared__ float sm[];
    float* Asm[2] = { sm, sm + AS_SZ };
    float* Bsm[2] = { sm + 2 * AS_SZ, sm + 2 * AS_SZ + BS_SZ };

    const float* Asrc = A;
    if (MODE == 0 && A == nullptr) Asrc = (const float*)g_attn;

    const int tid = threadIdx.x;
    const int wid = tid >> 5;
    const int lane = tid & 31;
    const int g = lane >> 2;        // groupID 0..7
    const int t4 = lane & 3;        // threadID-in-group 0..3
    const int wm = wid >> 1;        // 0..3 -> m offset
    const int wn = wid & 1;         // 0..1 -> n offset
    const int m0w = wm * 64;
    const int n0w = wn * 64;
    const int bm = blockIdx.y * BM;
    const int bn = blockIdx.x * BN;

    float acc[4][8][4];
#pragma unroll
    for (int ma = 0; ma < 4; ++ma)
#pragma unroll
        for (int na = 0; na < 8; ++na)
#pragma unroll
            for (int i = 0; i < 4; ++i) acc[ma][na][i] = 0.f;

    // --- async tile loader ---------------------------------------------------
    auto load_tile = [&](int kb, int buf) {
#pragma unroll
        for (int c = 0; c < 8; ++c) {               // A: 256x32 = 2048 16B chunks
            int id = tid + c * 256;
            int row = id >> 3;
            int kc = (id & 7) * 4;
            const float* src = Asrc + (long)(bm + row) * K + kb + kc;
            cp_async16(smem_u32(&Asm[buf][row * APITCH + kc]), src);
        }
#pragma unroll
        for (int c = 0; c < 4; ++c) {               // B: 32x128 = 1024 chunks
            int id = tid + c * 256;
            int kr = id >> 5;
            int nc = (id & 31) * 4;
            const float* src = W + (long)(kb + kr) * N + bn + nc;
            cp_async16(smem_u32(&Bsm[buf][kr * BPITCH + nc]), src);
        }
        cp_commit();
    };

    const int NIT = K / BK;
    load_tile(0, 0);

    int buf = 0;
    for (int it = 0; it < NIT; ++it) {
        cp_wait_all();
        __syncthreads();
        if (it + 1 < NIT) load_tile((it + 1) * BK, buf ^ 1);

        const float* As = Asm[buf];
        const float* Bs = Bsm[buf];
#pragma unroll
        for (int ks = 0; ks < 4; ++ks) {
            const int kk = ks * 8;
            uint32_t af[4][4];
            uint32_t bf[8][2];
#pragma unroll
            for (int ma = 0; ma < 4; ++ma) {
                const float* p = &As[(m0w + ma * 16 + g) * APITCH + kk + t4];
                af[ma][0] = cvt_tf32(p[0]);
                af[ma][1] = cvt_tf32(p[8 * APITCH]);
                af[ma][2] = cvt_tf32(p[4]);
                af[ma][3] = cvt_tf32(p[8 * APITCH + 4]);
            }
#pragma unroll
            for (int na = 0; na < 8; ++na) {
                const float* p = &Bs[(kk + t4) * BPITCH + n0w + na * 8 + g];
                bf[na][0] = cvt_tf32(p[0]);
                bf[na][1] = cvt_tf32(p[4 * BPITCH]);
            }
#pragma unroll
            for (int ma = 0; ma < 4; ++ma)
#pragma unroll
                for (int na = 0; na < 8; ++na)
                    mma_tf32(acc[ma][na], af[ma], bf[na]);
        }
        __syncthreads();
        buf ^= 1;
    }

    // --- epilogue ------------------------------------------------------------
#pragma unroll
    for (int na = 0; na < 8; ++na) {
        const int col = bn + n0w + na * 8 + 2 * t4;
        const float2 bx = *(const float2*)&bias[col];

        if (MODE == 0) {
#pragma unroll
            for (int ma = 0; ma < 4; ++ma) {
                const long r0 = bm + m0w + ma * 16 + g;
                float2 o0 = make_float2(acc[ma][na][0] + bx.x, acc[ma][na][1] + bx.y);
                float2 o1 = make_float2(acc[ma][na][2] + bx.x, acc[ma][na][3] + bx.y);
                *(float2*)&C[r0 * N + col] = o0;
                *(float2*)&C[(r0 + 8) * N + col] = o1;
            }
        } else {
            const int h = col / 192;
            const int rem = col - h * 192;
            const int which = rem >> 6;
            const int d = rem & 63;
            float* dst = (which == 0) ? g_q : (which == 1) ? g_k : g_v;
#pragma unroll
            for (int ma = 0; ma < 4; ++ma) {
                const int m = bm + m0w + ma * 16 + g;
                const int b = m >> 11;
                const int s = m & (S_ - 1);
                const long base = (((long)(b * H_ + h)) * S_ + s) * HD_ + d;
                float2 o0 = make_float2(acc[ma][na][0] + bx.x, acc[ma][na][1] + bx.y);
                float2 o1 = make_float2(acc[ma][na][2] + bx.x, acc[ma][na][3] + bx.y);
                *(float2*)&dst[base] = o0;
                *(float2*)&dst[base + 8 * HD_] = o1;   // row m+8, same b/h/d
            }
        }
    }
}

// ---------------------------------------------------------------------------
// Flash-style fp32 attention (unchanged from R2 — correct, ~0.9 ms).
// Block = (b, h, 64-query tile), 256 threads. Only ceil(vlen/64) key tiles:
// exp(masked - max) underflows to exactly 0 vs the -1e6 mask, bit-equivalent.
// ---------------------------------------------------------------------------
#define PT 68
#define ATTN_SMEM_BYTES ((4 * 64 * PT + 128) * 4)

__global__ __launch_bounds__(256) void attn_kernel(const int* __restrict__ val_lens)
{
    extern __shared__ float smf[];
    float* QsT = smf;                // [k][r] pre-scaled by 1/8
    float* KsT = QsT + 64 * PT;      // [k][c]
    float* Vs  = KsT + 64 * PT;      // [key][d]
    float* StT = Vs + 64 * PT;       // [c][r] scores -> probs
    float* alphas = StT + 64 * PT;
    float* lrow   = alphas + 64;

    const int q0 = blockIdx.x * 64;
    const int h  = blockIdx.y;
    const int b  = blockIdx.z;
    const int vlen = val_lens[b];
    const int tid = threadIdx.x;
    const int tx = tid & 15;
    const int ty = tid >> 4;
    const int lr = tid >> 2;
    const int d0 = (tid & 3) * 16;

    const long headoff = ((long)(b * H_ + h)) * S_ * HD_;
    const float* qbase = g_q + headoff;
    const float* kbase = g_k + headoff;
    const float* vbase = g_v + headoff;

    {
        const float* src = qbase + (long)(q0 + lr) * HD_ + d0;
#pragma unroll
        for (int j = 0; j < 16; j += 4) {
            float4 t4v = *(const float4*)(src + j);
            QsT[(d0 + j + 0) * PT + lr] = t4v.x * 0.125f;
            QsT[(d0 + j + 1) * PT + lr] = t4v.y * 0.125f;
            QsT[(d0 + j + 2) * PT + lr] = t4v.z * 0.125f;
            QsT[(d0 + j + 3) * PT + lr] = t4v.w * 0.125f;
        }
    }

    float mrow = -3.0e38f;
    float lacc = 0.f;
    float Oacc[4][4];
#pragma unroll
    for (int i = 0; i < 4; ++i)
#pragma unroll
        for (int j = 0; j < 4; ++j) Oacc[i][j] = 0.f;

    const int ntiles = (vlen + 63) >> 6;
    for (int kt = 0; kt < ntiles; ++kt) {
        {
            const float* ksrc = kbase + (long)(kt * 64 + lr) * HD_ + d0;
            const float* vsrc = vbase + (long)(kt * 64 + lr) * HD_ + d0;
#pragma unroll
            for (int j = 0; j < 16; j += 4) {
                float4 t4v = *(const float4*)(ksrc + j);
                KsT[(d0 + j + 0) * PT + lr] = t4v.x;
                KsT[(d0 + j + 1) * PT + lr] = t4v.y;
                KsT[(d0 + j + 2) * PT + lr] = t4v.z;
                KsT[(d0 + j + 3) * PT + lr] = t4v.w;
                *(float4*)&Vs[lr * PT + d0 + j] = *(const float4*)(vsrc + j);
            }
        }
        __syncthreads();

        {   // S = (Q*scale) K^T
            float acc[4][4];
#pragma unroll
            for (int i = 0; i < 4; ++i)
#pragma unroll
                for (int j = 0; j < 4; ++j) acc[i][j] = 0.f;
#pragma unroll 4
            for (int k = 0; k < 64; ++k) {
                float qa[4], kb[4];
                *(float4*)qa = *(const float4*)&QsT[k * PT + 4 * ty];
                *(float4*)kb = *(const float4*)&KsT[k * PT + 4 * tx];
#pragma unroll
                for (int i = 0; i < 4; ++i)
#pragma unroll
                    for (int j = 0; j < 4; ++j)
                        acc[i][j] += qa[i] * kb[j];
            }
#pragma unroll
            for (int j = 0; j < 4; ++j) {
                float4 c4 = make_float4(acc[0][j], acc[1][j], acc[2][j], acc[3][j]);
                *(float4*)&StT[(4 * tx + j) * PT + 4 * ty] = c4;
            }
        }
        __syncthreads();

        {   // online softmax; 4 consecutive lanes per row
            const int kg0 = kt * 64;
            float tmax = -3.0e38f;
#pragma unroll
            for (int j = 0; j < 16; ++j) {
                const int c = d0 + j;
                const float s = StT[c * PT + lr];
                if (kg0 + c < vlen) tmax = fmaxf(tmax, s);
            }
            tmax = fmaxf(tmax, __shfl_xor_sync(0xffffffffu, tmax, 1));
            tmax = fmaxf(tmax, __shfl_xor_sync(0xffffffffu, tmax, 2));
            const float mnew = fmaxf(mrow, tmax);
            const float alpha = __expf(mrow - mnew);
            float lsum = 0.f;
#pragma unroll
            for (int j = 0; j < 16; ++j) {
                const int c = d0 + j;
                const float s = StT[c * PT + lr];
                const float p = (kg0 + c < vlen) ? __expf(s - mnew) : 0.f;
                StT[c * PT + lr] = p;
                lsum += p;
            }
            lsum += __shfl_xor_sync(0xffffffffu, lsum, 1);
            lsum += __shfl_xor_sync(0xffffffffu, lsum, 2);
            lacc = lacc * alpha + lsum;
            mrow = mnew;
            if ((tid & 3) == 0) { alphas[lr] = alpha; lrow[lr] = lacc; }
        }
        __syncthreads();

        {   // O = O*alpha + P @ V
            float a[4];
#pragma unroll
            for (int i = 0; i < 4; ++i) a[i] = alphas[4 * ty + i];
#pragma unroll
            for (int i = 0; i < 4; ++i)
#pragma unroll
                for (int j = 0; j < 4; ++j) Oacc[i][j] *= a[i];
#pragma unroll 4
            for (int k = 0; k < 64; ++k) {
                float p[4], v[4];
                *(float4*)p = *(const float4*)&StT[k * PT + 4 * ty];
                *(float4*)v = *(const float4*)&Vs[k * PT + 4 * tx];
#pragma unroll
                for (int i = 0; i < 4; ++i)
#pragma unroll
                    for (int j = 0; j < 4; ++j)
                        Oacc[i][j] += p[i] * v[j];
            }
        }
        __syncthreads();
    }

    {
        float li[4];
#pragma unroll
        for (int i = 0; i < 4; ++i) li[i] = 1.0f / lrow[4 * ty + i];
#pragma unroll
        for (int i = 0; i < 4; ++i) {
            const long row = (long)b * S_ + q0 + 4 * ty + i;
            float4 o4 = make_float4(Oacc[i][0] * li[i], Oacc[i][1] * li[i],
                                    Oacc[i][2] * li[i], Oacc[i][3] * li[i]);
            *(float4*)&g_attn[row * D_ + h * HD_ + 4 * tx] = o4;
        }
    }
}

// ---------------------------------------------------------------------------
// Host launcher (graph-capturable: kernel launches only, no allocs/syncs)
// ---------------------------------------------------------------------------
extern "C" void kernel_launch(void* const* d_in, const int* in_sizes, int n_in,
                              void* d_out, int out_size)
{
    const float* x        = (const float*)d_in[0];
    const float* Wqkv     = (const float*)d_in[1];
    const float* bqkv     = (const float*)d_in[2];
    const float* Wout     = (const float*)d_in[3];
    const float* bout     = (const float*)d_in[4];
    const int*   val_lens = (const int*)d_in[5];
    float* out = (float*)d_out;

    cudaFuncSetAttribute(gemm_tf32<1>,
                         cudaFuncAttributeMaxDynamicSharedMemorySize,
                         GEMM_SMEM_BYTES);
    cudaFuncSetAttribute(gemm_tf32<0>,
                         cudaFuncAttributeMaxDynamicSharedMemorySize,
                         GEMM_SMEM_BYTES);
    cudaFuncSetAttribute(attn_kernel,
                         cudaFuncAttributeMaxDynamicSharedMemorySize,
                         ATTN_SMEM_BYTES);

    // 1) QKV projection (tensor cores), scattered into (B,H,S,HD) Q/K/V
    {
        dim3 grid((3 * D_) / BN, (B_ * S_) / BM);   // 24 x 32
        gemm_tf32<1><<<grid, 256, GEMM_SMEM_BYTES>>>(
            x, Wqkv, bqkv, nullptr, B_ * S_, 3 * D_, D_);
    }
    // 2) Flash attention -> g_attn
    {
        dim3 grid(S_ / 64, H_, B_);                 // 32 x 16 x 4
        attn_kernel<<<grid, 256, ATTN_SMEM_BYTES>>>(val_lens);
    }
    // 3) Output projection (tensor cores) -> d_out
    {
        dim3 grid(D_ / BN, (B_ * S_) / BM);         // 8 x 32
        gemm_tf32<0><<<grid, 256, GEMM_SMEM_BYTES>>>(
            nullptr, Wout, bout, out, B_ * S_, D_, D_);
    }
}

// round 5
// speedup vs baseline: 2.8399x; 1.6456x over previous
#include <cuda_runtime.h>
#include <cstdint>

#define B_ 4
#define S_ 2048
#define D_ 1024
#define H_ 16
#define HD_ 64

// ---------------------------------------------------------------------------
// Scratch (device globals: allocation-free per harness rules)
// ---------------------------------------------------------------------------
__device__ float g_q[B_ * H_ * S_ * HD_];
__device__ float g_k[B_ * H_ * S_ * HD_];
__device__ float g_v[B_ * H_ * S_ * HD_];
__device__ float g_attn[B_ * S_ * D_];

// ---------------------------------------------------------------------------
// PTX helpers
// ---------------------------------------------------------------------------
__device__ __forceinline__ uint32_t cvt_tf32(float x) {
    uint32_t r;
    asm("cvt.rna.tf32.f32 %0, %1;" : "=r"(r) : "f"(x));
    return r;
}
__device__ __forceinline__ uint32_t smem_u32(const void* p) {
    return (uint32_t)__cvta_generic_to_shared(p);
}
__device__ __forceinline__ void cp_async16(uint32_t dst, const void* src) {
    asm volatile("cp.async.cg.shared.global [%0], [%1], 16;" :: "r"(dst), "l"(src));
}
__device__ __forceinline__ void cp_commit() {
    asm volatile("cp.async.commit_group;" ::: "memory");
}
__device__ __forceinline__ void cp_wait1() {
    asm volatile("cp.async.wait_group 1;" ::: "memory");
}
__device__ __forceinline__ void cp_wait_all() {
    asm volatile("cp.async.wait_group 0;" ::: "memory");
}
__device__ __forceinline__ void mma_tf32(float* c, const uint32_t* a, const uint32_t* b) {
    asm("mma.sync.aligned.m16n8k8.row.col.f32.tf32.tf32.f32 "
        "{%0,%1,%2,%3}, {%4,%5,%6,%7}, {%8,%9}, {%0,%1,%2,%3};"
        : "+f"(c[0]), "+f"(c[1]), "+f"(c[2]), "+f"(c[3])
        : "r"(a[0]), "r"(a[1]), "r"(a[2]), "r"(a[3]),
          "r"(b[0]), "r"(b[1]));
}

// ---------------------------------------------------------------------------
// tf32 GEMM: C[M,N] = A[M,K] @ W[K,N] + bias.
// Block 128x128x32, 8 warps (2m x 4n), warp tile 64x32, 3-stage cp.async.
// __launch_bounds__(256,2): 2 CTAs/SM (regs<=128, smem 105KB/CTA).
// MODE 0: plain store to C; A==nullptr -> read g_attn.
// MODE 1: QKV scatter into g_q/g_k/g_v with (B,H,S,HD) layout.
// ---------------------------------------------------------------------------
#define BM 128
#define BN 128
#define BK 32
#define APITCH 36               // bank: 4g+t4 -> conflict-free fragments
#define BPITCH 136              // bank: 8t4+g -> conflict-free fragments
#define AS_SZ (BM * APITCH)     // 4608 floats
#define BS_SZ (BK * BPITCH)     // 4352 floats
#define STAGE_SZ (AS_SZ + BS_SZ)
#define GEMM_SMEM_BYTES (3 * STAGE_SZ * 4)   // 107520 B

template <int MODE>
__global__ __launch_bounds__(256, 2) void gemm_tf32(
    const float* __restrict__ A, const float* __restrict__ W,
    const float* __restrict__ bias, float* __restrict__ C,
    int M, int N, int K)
{
    extern __shared__ float sm[];

    const float* Asrc = A;
    if (MODE == 0 && A == nullptr) Asrc = (const float*)g_attn;

    const int tid = threadIdx.x;
    const int wid = tid >> 5;
    const int lane = tid & 31;
    const int g = lane >> 2;
    const int t4 = lane & 3;
    const int m0w = (wid >> 2) * 64;    // 2 m-warps
    const int n0w = (wid & 3) * 32;     // 4 n-warps
    const int bm = blockIdx.y * BM;
    const int bn = blockIdx.x * BN;

    float acc[4][4][4];
#pragma unroll
    for (int ma = 0; ma < 4; ++ma)
#pragma unroll
        for (int na = 0; na < 4; ++na)
#pragma unroll
            for (int i = 0; i < 4; ++i) acc[ma][na][i] = 0.f;

    // A: 128x32 -> 1024 16B chunks; B: 32x128 -> 1024 chunks. 4 each/thread.
    const int a_row = tid >> 1;              // reuse: id = tid + c*256
    auto load_tile = [&](int kb, int buf) {
        float* As = sm + buf * STAGE_SZ;
        float* Bs = As + AS_SZ;
#pragma unroll
        for (int c = 0; c < 4; ++c) {
            int id = tid + c * 256;
            int row = id >> 3;
            int kc = (id & 7) * 4;
            cp_async16(smem_u32(&As[row * APITCH + kc]),
                       Asrc + (long)(bm + row) * K + kb + kc);
        }
#pragma unroll
        for (int c = 0; c < 4; ++c) {
            int id = tid + c * 256;
            int kr = id >> 5;
            int nc = (id & 31) * 4;
            cp_async16(smem_u32(&Bs[kr * BPITCH + nc]),
                       W + (long)(kb + kr) * N + bn + nc);
        }
        cp_commit();
    };
    (void)a_row;

    const int NIT = K / BK;
    load_tile(0, 0);
    load_tile(BK, 1);

    for (int it = 0; it < NIT; ++it) {
        cp_wait1();
        __syncthreads();
        if (it + 2 < NIT) load_tile((it + 2) * BK, (it + 2) % 3);

        const float* As = sm + (it % 3) * STAGE_SZ;
        const float* Bs = As + AS_SZ;
#pragma unroll
        for (int ks = 0; ks < 4; ++ks) {
            const int kk = ks * 8;
            uint32_t af[4][4];
            uint32_t bf[4][2];
#pragma unroll
            for (int ma = 0; ma < 4; ++ma) {
                const float* p = &As[(m0w + ma * 16 + g) * APITCH + kk + t4];
                af[ma][0] = cvt_tf32(p[0]);
                af[ma][1] = cvt_tf32(p[8 * APITCH]);
                af[ma][2] = cvt_tf32(p[4]);
                af[ma][3] = cvt_tf32(p[8 * APITCH + 4]);
            }
#pragma unroll
            for (int na = 0; na < 4; ++na) {
                const float* p = &Bs[(kk + t4) * BPITCH + n0w + na * 8 + g];
                bf[na][0] = cvt_tf32(p[0]);
                bf[na][1] = cvt_tf32(p[4 * BPITCH]);
            }
#pragma unroll
            for (int ma = 0; ma < 4; ++ma)
#pragma unroll
                for (int na = 0; na < 4; ++na)
                    mma_tf32(acc[ma][na], af[ma], bf[na]);
        }
        __syncthreads();
    }

    // --- epilogue ------------------------------------------------------------
#pragma unroll
    for (int na = 0; na < 4; ++na) {
        const int col = bn + n0w + na * 8 + 2 * t4;
        const float2 bx = *(const float2*)&bias[col];

        if (MODE == 0) {
#pragma unroll
            for (int ma = 0; ma < 4; ++ma) {
                const long r0 = bm + m0w + ma * 16 + g;
                *(float2*)&C[r0 * N + col] =
                    make_float2(acc[ma][na][0] + bx.x, acc[ma][na][1] + bx.y);
                *(float2*)&C[(r0 + 8) * N + col] =
                    make_float2(acc[ma][na][2] + bx.x, acc[ma][na][3] + bx.y);
            }
        } else {
            const int h = col / 192;
            const int rem = col - h * 192;
            const int which = rem >> 6;
            const int d = rem & 63;
            float* dst = (which == 0) ? g_q : (which == 1) ? g_k : g_v;
#pragma unroll
            for (int ma = 0; ma < 4; ++ma) {
                const int m = bm + m0w + ma * 16 + g;
                const int b = m >> 11;
                const int s = m & (S_ - 1);
                const long base = (((long)(b * H_ + h)) * S_ + s) * HD_ + d;
                *(float2*)&dst[base] =
                    make_float2(acc[ma][na][0] + bx.x, acc[ma][na][1] + bx.y);
                *(float2*)&dst[base + 8 * HD_] =
                    make_float2(acc[ma][na][2] + bx.x, acc[ma][na][3] + bx.y);
            }
        }
    }
}

// ---------------------------------------------------------------------------
// Tensor-core flash attention. Block = (128-query tile, h, b), 256 thr, 8 warps.
// S = QK^T and O += P*V via tf32 m16n8k8; online softmax through smem.
// Only ceil(vlen/64) key tiles (exp underflow vs -1e6 mask is exactly 0).
// Warp w owns query rows [w*16, w*16+16); full 64-wide key/d dimension.
// ---------------------------------------------------------------------------
#define QT 128
#define AP 68
#define QS_OFF   0
#define KS_OFF   (QT * AP)                 // 8704
#define VS_OFF   (KS_OFF + 64 * AP)        // +4352
#define SS_OFF   (VS_OFF + 64 * AP)        // +4352
#define AL_OFF   (SS_OFF + QT * AP)        // +8704
#define LR_OFF   (AL_OFF + QT)
#define ATTN_SMEM_BYTES ((LR_OFF + QT) * 4)   // 105,984ish

__global__ __launch_bounds__(256, 2) void attn_tc(const int* __restrict__ val_lens)
{
    extern __shared__ float sm[];
    float* Qs  = sm + QS_OFF;    // [q][d]   pre-scaled by 1/8
    float* Ks  = sm + KS_OFF;    // [kk][d]  natural
    float* VsT = sm + VS_OFF;    // [d][kk]  transposed
    float* Ss  = sm + SS_OFF;    // [q][kk]  scores -> probs
    float* alphas = sm + AL_OFF;
    float* lrow   = sm + LR_OFF;

    const int q0 = blockIdx.x * QT;
    const int h  = blockIdx.y;
    const int b  = blockIdx.z;
    const int vlen = val_lens[b];
    const int tid = threadIdx.x;
    const int wid = tid >> 5;
    const int lane = tid & 31;
    const int g = lane >> 2;
    const int t4 = lane & 3;
    const int m0 = wid * 16;

    const long headoff = ((long)(b * H_ + h)) * S_ * HD_;
    const float* qbase = g_q + headoff;
    const float* kbase = g_k + headoff;
    const float* vbase = g_v + headoff;

    // Load Q tile (scaled by 1/8), natural layout.
    {
        const int r = tid >> 1;
        const int c0 = (tid & 1) * 32;
        const float* src = qbase + (long)(q0 + r) * HD_ + c0;
        float* dst = &Qs[r * AP + c0];
#pragma unroll
        for (int j = 0; j < 32; j += 4) {
            float4 v = *(const float4*)(src + j);
            v.x *= 0.125f; v.y *= 0.125f; v.z *= 0.125f; v.w *= 0.125f;
            *(float4*)(dst + j) = v;
        }
    }

    float mrow = -3.0e38f;
    float lacc = 0.f;
    float acc_o[8][4];
#pragma unroll
    for (int na = 0; na < 8; ++na)
#pragma unroll
        for (int i = 0; i < 4; ++i) acc_o[na][i] = 0.f;

    const int ntiles = (vlen + 63) >> 6;
    for (int kt = 0; kt < ntiles; ++kt) {
        // --- K tile via cp.async (natural [kk][d]) ---
#pragma unroll
        for (int c = 0; c < 4; ++c) {
            int id = tid + c * 256;
            int kk = id >> 4;
            int dc = (id & 15) * 4;
            cp_async16(smem_u32(&Ks[kk * AP + dc]),
                       kbase + (long)(kt * 64 + kk) * HD_ + dc);
        }
        cp_commit();
        // --- V tile, transposed store [d][kk] ---
        {
            const int vr = tid >> 2;
            const int vd0 = (tid & 3) * 16;
            const float* src = vbase + (long)(kt * 64 + vr) * HD_ + vd0;
#pragma unroll
            for (int j = 0; j < 16; j += 4) {
                float4 v = *(const float4*)(src + j);
                VsT[(vd0 + j + 0) * AP + vr] = v.x;
                VsT[(vd0 + j + 1) * AP + vr] = v.y;
                VsT[(vd0 + j + 2) * AP + vr] = v.z;
                VsT[(vd0 + j + 3) * AP + vr] = v.w;
            }
        }
        cp_wait_all();
        __syncthreads();

        // --- Phase A: S = Qs * Ks^T (warp: 16 q-rows x 64 kk) ---
        {
            float accs[8][4];
#pragma unroll
            for (int na = 0; na < 8; ++na)
#pragma unroll
                for (int i = 0; i < 4; ++i) accs[na][i] = 0.f;
#pragma unroll
            for (int kk = 0; kk < 64; kk += 8) {
                uint32_t af[4];
                const float* p = &Qs[(m0 + g) * AP + kk + t4];
                af[0] = cvt_tf32(p[0]);
                af[1] = cvt_tf32(p[8 * AP]);
                af[2] = cvt_tf32(p[4]);
                af[3] = cvt_tf32(p[8 * AP + 4]);
#pragma unroll
                for (int na = 0; na < 8; ++na) {
                    const float* q = &Ks[(na * 8 + g) * AP + kk + t4];
                    uint32_t bf[2] = { cvt_tf32(q[0]), cvt_tf32(q[4]) };
                    mma_tf32(accs[na], af, bf);
                }
            }
#pragma unroll
            for (int na = 0; na < 8; ++na) {
                *(float2*)&Ss[(m0 + g) * AP + na * 8 + 2 * t4] =
                    make_float2(accs[na][0], accs[na][1]);
                *(float2*)&Ss[(m0 + g + 8) * AP + na * 8 + 2 * t4] =
                    make_float2(accs[na][2], accs[na][3]);
            }
        }
        __syncthreads();

        // --- Phase B: online softmax (2 threads per row) ---
        {
            const int r = tid >> 1;
            const int c0 = (tid & 1) * 32;
            const int nvalid = vlen - kt * 64 - c0;  // valid cols in my segment
            float* row = &Ss[r * AP + c0];
            float tmax = -3.0e38f;
#pragma unroll
            for (int j = 0; j < 32; ++j) {
                float s = row[j];
                if (j < nvalid) tmax = fmaxf(tmax, s);
            }
            tmax = fmaxf(tmax, __shfl_xor_sync(0xffffffffu, tmax, 1));
            const float mnew = fmaxf(mrow, tmax);
            const float alpha = __expf(mrow - mnew);
            float lsum = 0.f;
#pragma unroll
            for (int j = 0; j < 32; ++j) {
                const float p = (j < nvalid) ? __expf(row[j] - mnew) : 0.f;
                row[j] = p;
                lsum += p;
            }
            lsum += __shfl_xor_sync(0xffffffffu, lsum, 1);
            lacc = lacc * alpha + lsum;
            mrow = mnew;
            if ((tid & 1) == 0) { alphas[r] = alpha; lrow[r] = lacc; }
        }
        __syncthreads();

        // --- Phase C: O = O*alpha + P * V ---
        {
            const float a_lo = alphas[m0 + g];
            const float a_hi = alphas[m0 + g + 8];
#pragma unroll
            for (int na = 0; na < 8; ++na) {
                acc_o[na][0] *= a_lo; acc_o[na][1] *= a_lo;
                acc_o[na][2] *= a_hi; acc_o[na][3] *= a_hi;
            }
#pragma unroll
            for (int kk = 0; kk < 64; kk += 8) {
                uint32_t af[4];
                const float* p = &Ss[(m0 + g) * AP + kk + t4];
                af[0] = cvt_tf32(p[0]);
                af[1] = cvt_tf32(p[8 * AP]);
                af[2] = cvt_tf32(p[4]);
                af[3] = cvt_tf32(p[8 * AP + 4]);
#pragma unroll
                for (int na = 0; na < 8; ++na) {
                    const float* q = &VsT[(na * 8 + g) * AP + kk + t4];
                    uint32_t bf[2] = { cvt_tf32(q[0]), cvt_tf32(q[4]) };
                    mma_tf32(acc_o[na], af, bf);
                }
            }
        }
        __syncthreads();   // protect Ks/VsT/Ss before next tile's loads
    }

    // --- epilogue: normalize, write g_attn (B,S,D) ---
    {
        const float li_lo = 1.0f / lrow[m0 + g];
        const float li_hi = 1.0f / lrow[m0 + g + 8];
        const long r0 = (long)b * S_ + q0 + m0 + g;
#pragma unroll
        for (int na = 0; na < 8; ++na) {
            const int col = h * HD_ + na * 8 + 2 * t4;
            *(float2*)&g_attn[r0 * D_ + col] =
                make_float2(acc_o[na][0] * li_lo, acc_o[na][1] * li_lo);
            *(float2*)&g_attn[(r0 + 8) * D_ + col] =
                make_float2(acc_o[na][2] * li_hi, acc_o[na][3] * li_hi);
        }
    }
}

// ---------------------------------------------------------------------------
// Host launcher (graph-capturable: kernel launches only, no allocs/syncs)
// ---------------------------------------------------------------------------
extern "C" void kernel_launch(void* const* d_in, const int* in_sizes, int n_in,
                              void* d_out, int out_size)
{
    const float* x        = (const float*)d_in[0];
    const float* Wqkv     = (const float*)d_in[1];
    const float* bqkv     = (const float*)d_in[2];
    const float* Wout     = (const float*)d_in[3];
    const float* bout     = (const float*)d_in[4];
    const int*   val_lens = (const int*)d_in[5];
    float* out = (float*)d_out;

    cudaFuncSetAttribute(gemm_tf32<1>,
                         cudaFuncAttributeMaxDynamicSharedMemorySize,
                         GEMM_SMEM_BYTES);
    cudaFuncSetAttribute(gemm_tf32<0>,
                         cudaFuncAttributeMaxDynamicSharedMemorySize,
                         GEMM_SMEM_BYTES);
    cudaFuncSetAttribute(attn_tc,
                         cudaFuncAttributeMaxDynamicSharedMemorySize,
                         ATTN_SMEM_BYTES);

    // 1) QKV projection (tensor cores), scattered into (B,H,S,HD) Q/K/V
    {
        dim3 grid((3 * D_) / BN, (B_ * S_) / BM);   // 24 x 64
        gemm_tf32<1><<<grid, 256, GEMM_SMEM_BYTES>>>(
            x, Wqkv, bqkv, nullptr, B_ * S_, 3 * D_, D_);
    }
    // 2) Tensor-core flash attention -> g_attn
    {
        dim3 grid(S_ / QT, H_, B_);                 // 16 x 16 x 4
        attn_tc<<<grid, 256, ATTN_SMEM_BYTES>>>(val_lens);
    }
    // 3) Output projection (tensor cores) -> d_out
    {
        dim3 grid(D_ / BN, (B_ * S_) / BM);         // 8 x 64
        gemm_tf32<0><<<grid, 256, GEMM_SMEM_BYTES>>>(
            nullptr, Wout, bout, out, B_ * S_, D_, D_);
    }
}